// round 16
// baseline (speedup 1.0000x reference)
#include <cuda_runtime.h>
#include <cuda_bf16.h>
#include <cstdint>

#define HD     1024
#define DIN    512
#define KTOT   1536
#define BATCH  64
#define LSEQ   512
#define NCTA   128
#define MROWS  32
#define NCHUNK 24
#define GCH    12                       // chunks per group (interleaved: c = 2*cg + g)
#define NSTAGE 3
#define TOTU   (LSEQ*GCH)
#define ATILE_ELEMS 2048                // 32x64 bf16
#define ATILE_BYTES 4096
#define BTILE_ELEMS 4096                // 64x64 bf16
#define BTILE_BYTES 8192
#define STAGE_BYTES (2*ATILE_BYTES + 2*BTILE_BYTES)   // 24576
#define CHUNK_TX 24576u
#define SMEM_STAGES (2*NSTAGE*STAGE_BYTES)            // 147456
#define GS_STRIDE 68
#define GS_SET (32*GS_STRIDE)
#define SMEM_DYN (1024 + SMEM_STAGES + 128 + 9*GS_SET*4 + 2048)   // + cs[512]

#define WSPLIT (128u*24*ATILE_ELEMS)
#define XSPLIT (512u*8*BTILE_ELEMS)

// ---------------- static device scratch ----------------
__device__ __nv_bfloat16 g_Wimg[2u*128*24*ATILE_ELEMS];
__device__ __nv_bfloat16 g_Ximg[2u*512*8*BTILE_ELEMS];
__device__ __nv_bfloat16 g_Himg[2u*2*16*BTILE_ELEMS];
__device__ unsigned g_barCnt;

// ---------------- helpers ----------------
__device__ __forceinline__ uint32_t smem_u32(const void* p) {
    uint32_t a;
    asm("{ .reg .u64 t; cvta.to.shared.u64 t, %1; cvt.u32.u64 %0, t; }" : "=r"(a) : "l"(p));
    return a;
}
__host__ __device__ __forceinline__ uint32_t sw128(uint32_t o) {
    return o ^ ((o >> 3) & 0x70);
}
__device__ __forceinline__ void mb_init(uint32_t a, uint32_t cnt) {
    asm volatile("mbarrier.init.shared.b64 [%0], %1;" :: "r"(a), "r"(cnt) : "memory");
}
__device__ __forceinline__ void mb_expect(uint32_t a, uint32_t bytes) {
    asm volatile("mbarrier.arrive.expect_tx.shared.b64 _, [%0], %1;" :: "r"(a), "r"(bytes) : "memory");
}
__device__ __forceinline__ void mb_arrive(uint32_t a) {
    asm volatile("mbarrier.arrive.shared.b64 _, [%0];" :: "r"(a) : "memory");
}
__device__ __forceinline__ void mb_wait(uint32_t a, uint32_t ph) {
    asm volatile(
        "{\n\t.reg .pred P;\n\t"
        "WL_%=:\n\t"
        "mbarrier.try_wait.parity.acquire.cta.shared::cta.b64 P, [%0], %1, 0x989680;\n\t"
        "@P bra.uni WD_%=;\n\t"
        "bra.uni WL_%=;\n\t"
        "WD_%=:\n\t}"
        :: "r"(a), "r"(ph) : "memory");
}
__device__ __forceinline__ void bulk_g2s(uint32_t dst, const void* src, uint32_t bytes, uint32_t mb) {
    asm volatile(
        "cp.async.bulk.shared::cta.global.mbarrier::complete_tx::bytes [%0], [%1], %2, [%3];"
        :: "r"(dst), "l"((unsigned long long)__cvta_generic_to_global(src)),
           "r"(bytes), "r"(mb) : "memory");
}
__device__ __forceinline__ void bar_named(int id, int cnt) {
    asm volatile("bar.sync %0, %1;" :: "r"(id), "r"(cnt) : "memory");
}
__device__ __forceinline__ void ldsm4(uint32_t* r, uint32_t addr) {
    asm volatile("ldmatrix.sync.aligned.m8n8.x4.shared.b16 {%0,%1,%2,%3}, [%4];"
                 : "=r"(r[0]), "=r"(r[1]), "=r"(r[2]), "=r"(r[3]) : "r"(addr));
}
__device__ __forceinline__ void mma_bf16(float* d, const uint32_t* a, const uint32_t* b) {
    asm volatile(
        "mma.sync.aligned.m16n8k16.row.col.f32.bf16.bf16.f32 "
        "{%0,%1,%2,%3}, {%4,%5,%6,%7}, {%8,%9}, {%0,%1,%2,%3};"
        : "+f"(d[0]), "+f"(d[1]), "+f"(d[2]), "+f"(d[3])
        : "r"(a[0]), "r"(a[1]), "r"(a[2]), "r"(a[3]), "r"(b[0]), "r"(b[1]));
}

// ---------------- prep kernels ----------------
__global__ void prep_w(const float* __restrict__ Wf, const float* __restrict__ Wi,
                       const float* __restrict__ Wc, const float* __restrict__ Wo) {
    uint32_t idx = blockIdx.x * 256 + threadIdx.x;
    if (idx >= 128u * 24 * MROWS * 64) return;
    uint32_t kcol = idx & 63;
    uint32_t rloc = (idx >> 6) & 31;
    uint32_t t2   = idx >> 11;
    uint32_t c    = t2 % 24;
    uint32_t b    = t2 / 24;
    uint32_t j    = b * 8 + (rloc >> 2);
    uint32_t gate = rloc & 3;
    uint32_t k    = c * 64 + kcol;
    const float* W = (gate == 0) ? Wf : (gate == 1) ? Wi : (gate == 2) ? Wc : Wo;
    float w = W[j * KTOT + k];
    __nv_bfloat16 hi = __float2bfloat16(w);
    __nv_bfloat16 lo = __float2bfloat16(w - __bfloat162float(hi));
    uint32_t e = sw128(rloc * 128 + kcol * 2) >> 1;
    uint32_t tile = (b * 24 + c) * ATILE_ELEMS;
    g_Wimg[tile + e] = hi;
    g_Wimg[WSPLIT + tile + e] = lo;
}

__global__ void prep_x(const int* __restrict__ x, const float* __restrict__ emb) {
    uint32_t idx = blockIdx.x * 256 + threadIdx.x;
    if (idx >= 512u * 8 * 64 * 64) return;
    uint32_t kcol = idx & 63;
    uint32_t n    = (idx >> 6) & 63;
    uint32_t c    = (idx >> 12) & 7;
    uint32_t t    = idx >> 15;
    int tok = x[t * BATCH + n];
    float v = emb[(size_t)tok * DIN + c * 64 + kcol];
    __nv_bfloat16 hi = __float2bfloat16(v);
    __nv_bfloat16 lo = __float2bfloat16(v - __bfloat162float(hi));
    uint32_t e = sw128(n * 128 + kcol * 2) >> 1;
    uint32_t off = (t * 8 + c) * BTILE_ELEMS;
    g_Ximg[off + e] = hi;
    g_Ximg[XSPLIT + off + e] = lo;
}

__global__ void prep_zero() {
    uint32_t idx = blockIdx.x * 256 + threadIdx.x;
    if (idx < 2u * 2 * 16 * BTILE_ELEMS) g_Himg[idx] = __float2bfloat16(0.f);
    if (idx == 0) g_barCnt = 0u;
}

// ---------------- persistent full-sequence kernel ----------------
// grid 128 CTAs (1/SM), 512 threads = 2 chunk-groups x (1m x 2n x 4k) warps.
// ALTERNATING EPILOGUE: group (t&1) runs reduce/update/publish for step t while
// the other group rolls into step t+1's (prefetched, X-based) chunks. c lives in smem.
__global__ __launch_bounds__(512, 1) void lstm_all(
    const float* __restrict__ bfp, const float* __restrict__ bip,
    const float* __restrict__ bcp, const float* __restrict__ bop,
    float* __restrict__ out) {

    extern __shared__ char smem_raw[];
    uint32_t sb0 = smem_u32(smem_raw);
    uint32_t sb  = (sb0 + 1023) & ~1023u;
    char* smem_al = smem_raw + (sb - sb0);

    const int tid = threadIdx.x;
    const int wid = tid >> 5;
    const int lid = tid & 31;
    const int b   = blockIdx.x;
    const int g   = wid >> 3;        // chunk-group
    const int gw  = wid & 7;
    const int wk  = gw >> 1;         // k16-slice within chunk
    const int wn  = gw & 1;          // n half
    const int n0  = wn * 32;

    const uint32_t barBase = sb + SMEM_STAGES;     // full[6] @ +s*8 ; consumed[6] @ +48+s*8
    float* gs  = (float*)(smem_al + SMEM_STAGES + 128);
    float* red = gs + 8 * GS_SET;
    float* cs  = red + GS_SET;       // c state [512]

    if (tid == 0) {
        for (int s = 0; s < 6; s++) { mb_init(barBase + s * 8, 1); mb_init(barBase + 48 + s * 8, 8); }
    }
    cs[tid] = 0.f;
    __syncthreads();

    // epilogue-role constants: this thread (tl in its group) updates elements
    // id = tl and id = tl + 256 when its group is the epilogue group.
    const int tl  = tid & 255;
    const int jlA = tl >> 6;          // 0..3
    const int jlB = jlA + 4;          // 4..7
    const int nnE = tl & 63;
    const float bfA = bfp[b * 8 + jlA], biA = bip[b * 8 + jlA],
                bcA = bcp[b * 8 + jlA], boA = bop[b * 8 + jlA];
    const float bfB = bfp[b * 8 + jlB], biB = bip[b * 8 + jlB],
                bcB = bcp[b * 8 + jlB], boB = bop[b * 8 + jlB];

    const bool prod = ((tid & 255) == 0);
    unsigned seenT = 0;

    uint32_t aoffs[2], boffs[2];
    {
        uint32_t arow = (uint32_t)(lid & 15);
        uint32_t khalf = ((uint32_t)(lid >> 4)) * 16;
        aoffs[0] = sw128((0  + arow) * 128 + wk * 32 + khalf);
        aoffs[1] = sw128((16 + arow) * 128 + wk * 32 + khalf);
        uint32_t br = (uint32_t)(((lid >> 4) << 3) + (lid & 7));
        uint32_t bk = (uint32_t)(((lid >> 3) & 1) << 4);
        boffs[0] = sw128((n0 +  0 + br) * 128 + wk * 32 + bk);
        boffs[1] = sw128((n0 + 16 + br) * 128 + wk * 32 + bk);
    }

    auto issue_load = [&](int u) {
        int tt = u / GCH, cg = u % GCH;
        int c  = 2 * cg + g;
        if (c >= 8 && (unsigned)tt > seenT) {        // memoized publish gate
            unsigned tgt = (unsigned)tt * NCTA;
            unsigned v;
            do {
                asm volatile("ld.acquire.gpu.u32 %0, [%1];" : "=r"(v) : "l"(&g_barCnt));
                if (v < tgt) __nanosleep(32);
            } while (v < tgt);
            seenT = (unsigned)tt;
            asm volatile("fence.proxy.async;" ::: "memory");
        }
        uint32_t sl  = (uint32_t)(g * NSTAGE + u % NSTAGE);
        uint32_t stg = sb + sl * STAGE_BYTES;
        uint32_t mb  = barBase + sl * 8;
        mb_expect(mb, CHUNK_TX);
        const __nv_bfloat16* aH = g_Wimg + (size_t)(b * 24 + c) * ATILE_ELEMS;
        const __nv_bfloat16* aL = aH + WSPLIT;
        const __nv_bfloat16 *bH, *bL;
        if (c < 8) {
            bH = g_Ximg + (size_t)(tt * 8 + c) * BTILE_ELEMS;
            bL = bH + XSPLIT;
        } else {
            int rb = (tt & 1) ^ 1;
            bH = g_Himg + (size_t)((0 * 2 + rb) * 16 + (c - 8)) * BTILE_ELEMS;
            bL = g_Himg + (size_t)((1 * 2 + rb) * 16 + (c - 8)) * BTILE_ELEMS;
        }
        bulk_g2s(stg,                  aH, ATILE_BYTES, mb);
        bulk_g2s(stg + ATILE_BYTES,    aL, ATILE_BYTES, mb);
        bulk_g2s(stg + 2*ATILE_BYTES,  bH, BTILE_BYTES, mb);
        bulk_g2s(stg + 2*ATILE_BYTES + BTILE_BYTES, bL, BTILE_BYTES, mb);
    };

    if (prod) { issue_load(0); issue_load(1); issue_load(2); }   // X-based

    for (int t = 0; t < LSEQ; t++) {
        float acc[8][4];
#pragma unroll
        for (int i = 0; i < 8; i++)
#pragma unroll
            for (int q = 0; q < 4; q++) acc[i][q] = 0.f;

        for (int cg = 0; cg < GCH; cg++) {
            int u = t * GCH + cg;
            uint32_t sl = (uint32_t)(g * NSTAGE + u % NSTAGE);
            uint32_t ph = (uint32_t)((u / NSTAGE) & 1);
            mb_wait(barBase + sl * 8, ph);

            uint32_t stg = sb + sl * STAGE_BYTES;
            uint32_t aHb = stg, aLb = stg + ATILE_BYTES;
            uint32_t bHb = stg + 2*ATILE_BYTES, bLb = bHb + BTILE_BYTES;

            uint32_t ah[8], al[8], bh[8], bl[8];
            ldsm4(ah,     aHb + aoffs[0]);
            ldsm4(ah + 4, aHb + aoffs[1]);
            ldsm4(al,     aLb + aoffs[0]);
            ldsm4(al + 4, aLb + aoffs[1]);
            ldsm4(bh,     bHb + boffs[0]);
            ldsm4(bh + 4, bHb + boffs[1]);
            ldsm4(bl,     bLb + boffs[0]);
            ldsm4(bl + 4, bLb + boffs[1]);

#pragma unroll
            for (int mt = 0; mt < 2; mt++) {
                const uint32_t* aH4 = ah + mt * 4;
                const uint32_t* aL4 = al + mt * 4;
#pragma unroll
                for (int nt = 0; nt < 4; nt++) {
                    float* d = acc[mt * 4 + nt];
                    const uint32_t* bH2 = bh + nt * 2;
                    const uint32_t* bL2 = bl + nt * 2;
                    mma_bf16(d, aH4, bH2);
                    mma_bf16(d, aH4, bL2);
                    mma_bf16(d, aL4, bH2);
                }
            }
            if (lid == 0) mb_arrive(barBase + 48 + sl * 8);
            if (prod && u + NSTAGE < TOTU) {
                mb_wait(barBase + 48 + sl * 8, ph);   // stage free
                issue_load(u + NSTAGE);
            }
        }

        // barrier #1: prior epilogue group done reading gs (it arrives here late)
        __syncthreads();
        // write k-partials: set p = g*4 + wk
        {
            float* gsb = gs + (g * 4 + wk) * GS_SET;
            int rr  = lid >> 2;
            int cc0 = (lid & 3) * 2;
#pragma unroll
            for (int mt = 0; mt < 2; mt++)
#pragma unroll
                for (int nt = 0; nt < 4; nt++) {
                    float* d = acc[mt * 4 + nt];
                    int r  = mt * 16 + rr;
                    int cc = n0 + nt * 8 + cc0;
                    gsb[r * GS_STRIDE + cc]           = d[0];
                    gsb[r * GS_STRIDE + cc + 1]       = d[1];
                    gsb[(r + 8) * GS_STRIDE + cc]     = d[2];
                    gsb[(r + 8) * GS_STRIDE + cc + 1] = d[3];
                }
        }
        // barrier #2: all partials visible
        __syncthreads();

        // ---- alternating epilogue: group (t&1) only; other group rolls on ----
        if (g == (t & 1)) {
            // reduce 8 partial sets -> red (256 threads, 8 floats each)
            {
                int r  = tl >> 3;
                int nq = (tl & 7) * 8;
                float4 s0 = make_float4(0.f, 0.f, 0.f, 0.f);
                float4 s1 = make_float4(0.f, 0.f, 0.f, 0.f);
#pragma unroll
                for (int p = 0; p < 8; p++) {
                    const float* base = gs + (p * GS_SET + r * GS_STRIDE + nq);
                    float4 v0 = *(const float4*)(base);
                    float4 v1 = *(const float4*)(base + 4);
                    s0.x += v0.x; s0.y += v0.y; s0.z += v0.z; s0.w += v0.w;
                    s1.x += v1.x; s1.y += v1.y; s1.z += v1.z; s1.w += v1.w;
                }
                *(float4*)(red + r * GS_STRIDE + nq)     = s0;
                *(float4*)(red + r * GS_STRIDE + nq + 4) = s1;
            }
            bar_named(2 + g, 256);
            // state update: 2 elements per thread
            int wbuf = t & 1;
#pragma unroll
            for (int u2 = 0; u2 < 2; u2++) {
                int id = u2 * 256 + tl;
                int jl = (u2 == 0) ? jlA : jlB;
                int jg = b * 8 + jl;
                float bfv = (u2 == 0) ? bfA : bfB;
                float biv = (u2 == 0) ? biA : biB;
                float bcv = (u2 == 0) ? bcA : bcB;
                float bov = (u2 == 0) ? boA : boB;
                float pf = red[(jl * 4 + 0) * GS_STRIDE + nnE] + bfv;
                float pi = red[(jl * 4 + 1) * GS_STRIDE + nnE] + biv;
                float pc = red[(jl * 4 + 2) * GS_STRIDE + nnE] + bcv;
                float po = red[(jl * 4 + 3) * GS_STRIDE + nnE] + bov;
                float f  = 1.f / (1.f + __expf(-pf));
                float i_ = 1.f / (1.f + __expf(-pi));
                float o  = 1.f / (1.f + __expf(-po));
                float cold = cs[id];
                float cnew = f * cold + i_ * tanhf(pc);
                float h    = o * tanhf(cnew);
                cs[id] = cnew;
                out[((size_t)t * BATCH + nnE) * HD + jg] = h;
                if (t == LSEQ - 1) {
                    size_t base = (size_t)LSEQ * BATCH * HD;
                    out[base + nnE * HD + jg] = cnew;
                    out[base + BATCH * HD + nnE * HD + jg] = h;
                }
                __nv_bfloat16 hh = __float2bfloat16(h);
                __nv_bfloat16 hl = __float2bfloat16(h - __bfloat162float(hh));
                uint32_t hci = (uint32_t)jg >> 6;
                uint32_t hsw = sw128((uint32_t)nnE * 128 + ((uint32_t)jg & 63) * 2) >> 1;
                g_Himg[((0u * 2 + wbuf) * 16 + hci) * BTILE_ELEMS + hsw] = hh;
                g_Himg[((1u * 2 + wbuf) * 16 + hci) * BTILE_ELEMS + hsw] = hl;
            }
            // publish step t (group-local barrier, then one atomicAdd)
            if (t < LSEQ - 1) {
                __threadfence();
                bar_named(2 + g, 256);
                if (tl == 0) atomicAdd(&g_barCnt, 1u);
            }
        }
        // non-epilogue group falls through to step t+1 immediately
    }
}

extern "C" void kernel_launch(void* const* d_in, const int* in_sizes, int n_in,
                              void* d_out, int out_size) {
    const int*   x   = (const int*)d_in[0];
    const float* emb = (const float*)d_in[1];
    const float* Wf  = (const float*)d_in[2];
    const float* bf  = (const float*)d_in[3];
    const float* Wi  = (const float*)d_in[4];
    const float* bi  = (const float*)d_in[5];
    const float* Wc  = (const float*)d_in[6];
    const float* bc  = (const float*)d_in[7];
    const float* Wo  = (const float*)d_in[8];
    const float* bo  = (const float*)d_in[9];
    float* out = (float*)d_out;

    static bool attr_set = false;
    if (!attr_set) {
        cudaFuncSetAttribute(lstm_all, cudaFuncAttributeMaxDynamicSharedMemorySize, SMEM_DYN);
        attr_set = true;
    }

    prep_w<<<(128u * 24 * MROWS * 64 + 255) / 256, 256>>>(Wf, Wi, Wc, Wo);
    prep_x<<<(512u * 8 * 64 * 64 + 255) / 256, 256>>>(x, emb);
    prep_zero<<<(2u * 2 * 16 * BTILE_ELEMS + 255) / 256, 256>>>();

    lstm_all<<<NCTA, 512, SMEM_DYN>>>(bf, bi, bc, bo, out);
}

// round 17
// speedup vs baseline: 1.1063x; 1.1063x over previous
#include <cuda_runtime.h>
#include <cuda_bf16.h>
#include <cstdint>

#define HD     1024
#define DIN    512
#define KTOT   1536
#define BATCH  64
#define LSEQ   512
#define NCTA   128
#define MROWS  32
#define NCHUNK 24
#define GCH    12                       // chunks per group (interleaved: c = 2*cg + g)
#define NSTAGE 3
#define TOTU   (LSEQ*GCH)
#define ATILE_ELEMS 2048                // 32x64 bf16
#define ATILE_BYTES 4096
#define BTILE_ELEMS 4096                // 64x64 bf16
#define BTILE_BYTES 8192
#define STAGE_BYTES (2*ATILE_BYTES + 2*BTILE_BYTES)   // 24576
#define CHUNK_TX 24576u
#define SMEM_STAGES (2*NSTAGE*STAGE_BYTES)            // 147456
#define GS_STRIDE 68
#define GS_SET (32*GS_STRIDE)
#define SMEM_DYN (1024 + SMEM_STAGES + 128 + 8*GS_SET*4)   // ~218KB

#define WSPLIT (128u*24*ATILE_ELEMS)
#define XSPLIT (512u*8*BTILE_ELEMS)

// ---------------- static device scratch ----------------
__device__ __nv_bfloat16 g_Wimg[2u*128*24*ATILE_ELEMS];
__device__ __nv_bfloat16 g_Ximg[2u*512*8*BTILE_ELEMS];
__device__ __nv_bfloat16 g_Himg[2u*2*16*BTILE_ELEMS];
__device__ unsigned g_barCnt;

// ---------------- helpers ----------------
__device__ __forceinline__ uint32_t smem_u32(const void* p) {
    uint32_t a;
    asm("{ .reg .u64 t; cvta.to.shared.u64 t, %1; cvt.u32.u64 %0, t; }" : "=r"(a) : "l"(p));
    return a;
}
__host__ __device__ __forceinline__ uint32_t sw128(uint32_t o) {
    return o ^ ((o >> 3) & 0x70);
}
__device__ __forceinline__ void mb_init(uint32_t a, uint32_t cnt) {
    asm volatile("mbarrier.init.shared.b64 [%0], %1;" :: "r"(a), "r"(cnt) : "memory");
}
__device__ __forceinline__ void mb_expect(uint32_t a, uint32_t bytes) {
    asm volatile("mbarrier.arrive.expect_tx.shared.b64 _, [%0], %1;" :: "r"(a), "r"(bytes) : "memory");
}
__device__ __forceinline__ void mb_arrive(uint32_t a) {
    asm volatile("mbarrier.arrive.shared.b64 _, [%0];" :: "r"(a) : "memory");
}
__device__ __forceinline__ void mb_wait(uint32_t a, uint32_t ph) {
    asm volatile(
        "{\n\t.reg .pred P;\n\t"
        "WL_%=:\n\t"
        "mbarrier.try_wait.parity.acquire.cta.shared::cta.b64 P, [%0], %1, 0x989680;\n\t"
        "@P bra.uni WD_%=;\n\t"
        "bra.uni WL_%=;\n\t"
        "WD_%=:\n\t}"
        :: "r"(a), "r"(ph) : "memory");
}
__device__ __forceinline__ void bulk_g2s(uint32_t dst, const void* src, uint32_t bytes, uint32_t mb) {
    asm volatile(
        "cp.async.bulk.shared::cta.global.mbarrier::complete_tx::bytes [%0], [%1], %2, [%3];"
        :: "r"(dst), "l"((unsigned long long)__cvta_generic_to_global(src)),
           "r"(bytes), "r"(mb) : "memory");
}
__device__ __forceinline__ void ldsm4(uint32_t* r, uint32_t addr) {
    asm volatile("ldmatrix.sync.aligned.m8n8.x4.shared.b16 {%0,%1,%2,%3}, [%4];"
                 : "=r"(r[0]), "=r"(r[1]), "=r"(r[2]), "=r"(r[3]) : "r"(addr));
}
__device__ __forceinline__ void mma_bf16(float* d, const uint32_t* a, const uint32_t* b) {
    asm volatile(
        "mma.sync.aligned.m16n8k16.row.col.f32.bf16.bf16.f32 "
        "{%0,%1,%2,%3}, {%4,%5,%6,%7}, {%8,%9}, {%0,%1,%2,%3};"
        : "+f"(d[0]), "+f"(d[1]), "+f"(d[2]), "+f"(d[3])
        : "r"(a[0]), "r"(a[1]), "r"(a[2]), "r"(a[3]), "r"(b[0]), "r"(b[1]));
}

// ---------------- prep kernels ----------------
__global__ void prep_w(const float* __restrict__ Wf, const float* __restrict__ Wi,
                       const float* __restrict__ Wc, const float* __restrict__ Wo) {
    uint32_t idx = blockIdx.x * 256 + threadIdx.x;
    if (idx >= 128u * 24 * MROWS * 64) return;
    uint32_t kcol = idx & 63;
    uint32_t rloc = (idx >> 6) & 31;
    uint32_t t2   = idx >> 11;
    uint32_t c    = t2 % 24;
    uint32_t b    = t2 / 24;
    uint32_t j    = b * 8 + (rloc >> 2);
    uint32_t gate = rloc & 3;
    uint32_t k    = c * 64 + kcol;
    const float* W = (gate == 0) ? Wf : (gate == 1) ? Wi : (gate == 2) ? Wc : Wo;
    float w = W[j * KTOT + k];
    __nv_bfloat16 hi = __float2bfloat16(w);
    __nv_bfloat16 lo = __float2bfloat16(w - __bfloat162float(hi));
    uint32_t e = sw128(rloc * 128 + kcol * 2) >> 1;
    uint32_t tile = (b * 24 + c) * ATILE_ELEMS;
    g_Wimg[tile + e] = hi;
    g_Wimg[WSPLIT + tile + e] = lo;
}

__global__ void prep_x(const int* __restrict__ x, const float* __restrict__ emb) {
    uint32_t idx = blockIdx.x * 256 + threadIdx.x;
    if (idx >= 512u * 8 * 64 * 64) return;
    uint32_t kcol = idx & 63;
    uint32_t n    = (idx >> 6) & 63;
    uint32_t c    = (idx >> 12) & 7;
    uint32_t t    = idx >> 15;
    int tok = x[t * BATCH + n];
    float v = emb[(size_t)tok * DIN + c * 64 + kcol];
    __nv_bfloat16 hi = __float2bfloat16(v);
    __nv_bfloat16 lo = __float2bfloat16(v - __bfloat162float(hi));
    uint32_t e = sw128(n * 128 + kcol * 2) >> 1;
    uint32_t off = (t * 8 + c) * BTILE_ELEMS;
    g_Ximg[off + e] = hi;
    g_Ximg[XSPLIT + off + e] = lo;
}

__global__ void prep_zero() {
    uint32_t idx = blockIdx.x * 256 + threadIdx.x;
    if (idx < 2u * 2 * 16 * BTILE_ELEMS) g_Himg[idx] = __float2bfloat16(0.f);
    if (idx == 0) g_barCnt = 0u;
}

// ---------------- persistent full-sequence kernel ----------------
// grid 128 CTAs (1/SM), 512 threads = 2 chunk-groups x (1m x 2n x 4k) warps.
// Inline producers (tid 0 / tid 256) with memoized publish gate (R14).
// R17: fused epilogue — partials write needs no preceding barrier (disjoint
// regions, ordered by previous publish barrier); reduce+update fused per
// thread (no red buffer). 2 CTA barriers/step instead of 4.
__global__ __launch_bounds__(512, 1) void lstm_all(
    const float* __restrict__ bfp, const float* __restrict__ bip,
    const float* __restrict__ bcp, const float* __restrict__ bop,
    float* __restrict__ out) {

    extern __shared__ char smem_raw[];
    uint32_t sb0 = smem_u32(smem_raw);
    uint32_t sb  = (sb0 + 1023) & ~1023u;
    char* smem_al = smem_raw + (sb - sb0);

    const int tid = threadIdx.x;
    const int wid = tid >> 5;
    const int lid = tid & 31;
    const int b   = blockIdx.x;
    const int g   = wid >> 3;        // chunk-group
    const int gw  = wid & 7;
    const int wk  = gw >> 1;         // k16-slice within chunk
    const int wn  = gw & 1;          // n half
    const int n0  = wn * 32;

    const uint32_t barBase = sb + SMEM_STAGES;     // full[6] @ +s*8 ; consumed[6] @ +48+s*8
    float* gs = (float*)(smem_al + SMEM_STAGES + 128);   // 8 partial sets [32][68]

    if (tid == 0) {
        for (int s = 0; s < 6; s++) { mb_init(barBase + s * 8, 1); mb_init(barBase + 48 + s * 8, 8); }
    }
    __syncthreads();

    const int jl = tid >> 6;
    const int nn = tid & 63;
    const int jg = b * 8 + jl;
    const float bfr = bfp[jg], bir = bip[jg], bcr = bcp[jg], bor = bop[jg];
    float creg = 0.f;
    const uint32_t hsw = sw128((uint32_t)nn * 128 + ((uint32_t)jg & 63) * 2) >> 1;
    const uint32_t hci = (uint32_t)jg >> 6;

    const bool prod = ((tid & 255) == 0);
    unsigned seenT = 0;

    uint32_t aoffs[2], boffs[2];
    {
        uint32_t arow = (uint32_t)(lid & 15);
        uint32_t khalf = ((uint32_t)(lid >> 4)) * 16;
        aoffs[0] = sw128((0  + arow) * 128 + wk * 32 + khalf);
        aoffs[1] = sw128((16 + arow) * 128 + wk * 32 + khalf);
        uint32_t br = (uint32_t)(((lid >> 4) << 3) + (lid & 7));
        uint32_t bk = (uint32_t)(((lid >> 3) & 1) << 4);
        boffs[0] = sw128((n0 +  0 + br) * 128 + wk * 32 + bk);
        boffs[1] = sw128((n0 + 16 + br) * 128 + wk * 32 + bk);
    }

    auto issue_load = [&](int u) {
        int tt = u / GCH, cg = u % GCH;
        int c  = 2 * cg + g;
        if (c >= 8 && (unsigned)tt > seenT) {        // memoized publish gate
            unsigned tgt = (unsigned)tt * NCTA;
            unsigned v;
            do {
                asm volatile("ld.acquire.gpu.u32 %0, [%1];" : "=r"(v) : "l"(&g_barCnt));
                if (v < tgt) __nanosleep(32);
            } while (v < tgt);
            seenT = (unsigned)tt;
            asm volatile("fence.proxy.async;" ::: "memory");
        }
        uint32_t sl  = (uint32_t)(g * NSTAGE + u % NSTAGE);
        uint32_t stg = sb + sl * STAGE_BYTES;
        uint32_t mb  = barBase + sl * 8;
        mb_expect(mb, CHUNK_TX);
        const __nv_bfloat16* aH = g_Wimg + (size_t)(b * 24 + c) * ATILE_ELEMS;
        const __nv_bfloat16* aL = aH + WSPLIT;
        const __nv_bfloat16 *bH, *bL;
        if (c < 8) {
            bH = g_Ximg + (size_t)(tt * 8 + c) * BTILE_ELEMS;
            bL = bH + XSPLIT;
        } else {
            int rb = (tt & 1) ^ 1;
            bH = g_Himg + (size_t)((0 * 2 + rb) * 16 + (c - 8)) * BTILE_ELEMS;
            bL = g_Himg + (size_t)((1 * 2 + rb) * 16 + (c - 8)) * BTILE_ELEMS;
        }
        bulk_g2s(stg,                  aH, ATILE_BYTES, mb);
        bulk_g2s(stg + ATILE_BYTES,    aL, ATILE_BYTES, mb);
        bulk_g2s(stg + 2*ATILE_BYTES,  bH, BTILE_BYTES, mb);
        bulk_g2s(stg + 2*ATILE_BYTES + BTILE_BYTES, bL, BTILE_BYTES, mb);
    };

    if (prod) { issue_load(0); issue_load(1); issue_load(2); }   // X-based

    for (int t = 0; t < LSEQ; t++) {
        float acc[8][4];
#pragma unroll
        for (int i = 0; i < 8; i++)
#pragma unroll
            for (int q = 0; q < 4; q++) acc[i][q] = 0.f;

        for (int cg = 0; cg < GCH; cg++) {
            int u = t * GCH + cg;
            uint32_t sl = (uint32_t)(g * NSTAGE + u % NSTAGE);
            uint32_t ph = (uint32_t)((u / NSTAGE) & 1);
            mb_wait(barBase + sl * 8, ph);

            uint32_t stg = sb + sl * STAGE_BYTES;
            uint32_t aHb = stg, aLb = stg + ATILE_BYTES;
            uint32_t bHb = stg + 2*ATILE_BYTES, bLb = bHb + BTILE_BYTES;

            uint32_t ah[8], al[8], bh[8], bl[8];
            ldsm4(ah,     aHb + aoffs[0]);
            ldsm4(ah + 4, aHb + aoffs[1]);
            ldsm4(al,     aLb + aoffs[0]);
            ldsm4(al + 4, aLb + aoffs[1]);
            ldsm4(bh,     bHb + boffs[0]);
            ldsm4(bh + 4, bHb + boffs[1]);
            ldsm4(bl,     bLb + boffs[0]);
            ldsm4(bl + 4, bLb + boffs[1]);

#pragma unroll
            for (int mt = 0; mt < 2; mt++) {
                const uint32_t* aH4 = ah + mt * 4;
                const uint32_t* aL4 = al + mt * 4;
#pragma unroll
                for (int nt = 0; nt < 4; nt++) {
                    float* d = acc[mt * 4 + nt];
                    const uint32_t* bH2 = bh + nt * 2;
                    const uint32_t* bL2 = bl + nt * 2;
                    mma_bf16(d, aH4, bH2);
                    mma_bf16(d, aH4, bL2);
                    mma_bf16(d, aL4, bH2);
                }
            }
            if (lid == 0) mb_arrive(barBase + 48 + sl * 8);
            if (prod && u + NSTAGE < TOTU) {
                mb_wait(barBase + 48 + sl * 8, ph);   // stage free
                issue_load(u + NSTAGE);
            }
        }

        // write k-partials directly (disjoint regions per (g,wk,wn);
        // previous step's gs reads were sealed by the publish barrier)
        {
            float* gsb = gs + (g * 4 + wk) * GS_SET;
            int rr  = lid >> 2;
            int cc0 = (lid & 3) * 2;
#pragma unroll
            for (int mt = 0; mt < 2; mt++)
#pragma unroll
                for (int nt = 0; nt < 4; nt++) {
                    float* d = acc[mt * 4 + nt];
                    int r  = mt * 16 + rr;
                    int cc = n0 + nt * 8 + cc0;
                    gsb[r * GS_STRIDE + cc]           = d[0];
                    gsb[r * GS_STRIDE + cc + 1]       = d[1];
                    gsb[(r + 8) * GS_STRIDE + cc]     = d[2];
                    gsb[(r + 8) * GS_STRIDE + cc + 1] = d[3];
                }
        }
        __syncthreads();    // all partials visible

        // fused reduce + state update (1 element/thread)
        {
            float pg[4];
#pragma unroll
            for (int q = 0; q < 4; q++) {
                const float* base = gs + (jl * 4 + q) * GS_STRIDE + nn;
                float s = 0.f;
#pragma unroll
                for (int p = 0; p < 8; p++) s += base[p * GS_SET];
                pg[q] = s;
            }
            float pf = pg[0] + bfr;
            float pi = pg[1] + bir;
            float pc = pg[2] + bcr;
            float po = pg[3] + bor;
            float f  = 1.f / (1.f + __expf(-pf));
            float i_ = 1.f / (1.f + __expf(-pi));
            float o  = 1.f / (1.f + __expf(-po));
            float cnew = f * creg + i_ * tanhf(pc);
            float h    = o * tanhf(cnew);
            creg = cnew;
            out[((size_t)t * BATCH + nn) * HD + jg] = h;
            if (t == LSEQ - 1) {
                size_t base = (size_t)LSEQ * BATCH * HD;
                out[base + nn * HD + jg] = cnew;
                out[base + BATCH * HD + nn * HD + jg] = h;
            }
            int wbuf = t & 1;
            __nv_bfloat16 hh = __float2bfloat16(h);
            __nv_bfloat16 hl = __float2bfloat16(h - __bfloat162float(hh));
            g_Himg[((0u * 2 + wbuf) * 16 + hci) * BTILE_ELEMS + hsw] = hh;
            g_Himg[((1u * 2 + wbuf) * 16 + hci) * BTILE_ELEMS + hsw] = hl;
        }

        // publish step t (this barrier also seals gs reads vs next step's writes)
        if (t < LSEQ - 1) {
            __threadfence();
            __syncthreads();
            if (tid == 0) atomicAdd(&g_barCnt, 1u);
        }
    }
}

extern "C" void kernel_launch(void* const* d_in, const int* in_sizes, int n_in,
                              void* d_out, int out_size) {
    const int*   x   = (const int*)d_in[0];
    const float* emb = (const float*)d_in[1];
    const float* Wf  = (const float*)d_in[2];
    const float* bf  = (const float*)d_in[3];
    const float* Wi  = (const float*)d_in[4];
    const float* bi  = (const float*)d_in[5];
    const float* Wc  = (const float*)d_in[6];
    const float* bc  = (const float*)d_in[7];
    const float* Wo  = (const float*)d_in[8];
    const float* bo  = (const float*)d_in[9];
    float* out = (float*)d_out;

    static bool attr_set = false;
    if (!attr_set) {
        cudaFuncSetAttribute(lstm_all, cudaFuncAttributeMaxDynamicSharedMemorySize, SMEM_DYN);
        attr_set = true;
    }

    prep_w<<<(128u * 24 * MROWS * 64 + 255) / 256, 256>>>(Wf, Wi, Wc, Wo);
    prep_x<<<(512u * 8 * 64 * 64 + 255) / 256, 256>>>(x, emb);
    prep_zero<<<(2u * 2 * 16 * BTILE_ELEMS + 255) / 256, 256>>>();

    lstm_all<<<NCTA, 512, SMEM_DYN>>>(bf, bi, bc, bo, out);
}